// round 15
// baseline (speedup 1.0000x reference)
#include <cuda_runtime.h>
#include <cuda_bf16.h>

#define BB 8
#define NN 2048
#define NPAD (NN + 512)
#define BIGF 1e30f
#define FARF 1e15f

// shape: block = 64 thr (2 warps); grid (QCH, RSP, BB) = (16, 32, 8) = 4096
#define TBC 64
#define QCH 16
#define RSP 32
#define ARR (QCH * RSP)          // 512 arrivals per batch-task

// Scratch (allocation-free). Points transformed: (x+y, x-y, z, 0).
// g_valid[0]=clean(points+target), g_valid[1]=predp(points+pred)
__device__ __align__(16) float4       g_valid[2][BB][NPAD];
__device__ __align__(16) unsigned int g_minbits[2][BB][NN];  // [0]=row(clean) [1]=col(pred)
__device__ int          g_cnt[BB];
__device__ float        g_l1part[128];
__device__ float        g_tasksum[BB];
__device__ unsigned int g_done_task[BB];
__device__ unsigned int g_done;

// ---------------------------------------------------------------------------
// Kernel 1: prep — 128 blocks x 128 threads, one point per thread (unchanged).
// ---------------------------------------------------------------------------
__global__ void __launch_bounds__(128)
prep_kernel(const float* __restrict__ pred,
            const float* __restrict__ target,
            const int*   __restrict__ mask,
            const float* __restrict__ points) {
    int bid = blockIdx.x, tid = threadIdx.x;
    int b = bid >> 4, s = bid & 15;
    int n  = s * 128 + tid;
    int gi = b * NN + n;

    const float* pp = pred   + gi * 3;
    const float* tt = target + gi * 3;
    const float* xx = points + gi * 3;
    float p0 = pp[0], p1 = pp[1], p2 = pp[2];
    float t0 = tt[0], t1 = tt[1], t2 = tt[2];
    float x0 = xx[0], x1 = xx[1], x2 = xx[2];
    int m = mask[gi];

    const unsigned bigbits = __float_as_uint(BIGF);
    g_minbits[0][b][n] = bigbits;
    g_minbits[1][b][n] = bigbits;

    float c0 = x0 + t0, c1 = x1 + t1, c2 = x2 + t2;   // clean
    float q0 = x0 + p0, q1 = x1 + p1, q2 = x2 + p2;   // predp
    float l1 = 0.f;

    __shared__ int sh_cnt, sh_base;
    if (tid == 0) sh_cnt = 0;
    __syncthreads();
    int klocal = -1;
    if (m) {
        l1 = fabsf(p0 - t0) + fabsf(p1 - t1) + fabsf(p2 - t2);
        klocal = atomicAdd(&sh_cnt, 1);
    }
    __syncthreads();
    if (tid == 0) sh_base = atomicAdd(&g_cnt[b], sh_cnt);

    __shared__ float wsum[4];
#pragma unroll
    for (int o = 16; o > 0; o >>= 1) l1 += __shfl_down_sync(0xffffffffu, l1, o);
    if ((tid & 31) == 0) wsum[tid >> 5] = l1;
    __syncthreads();
    if (tid == 0)
        g_l1part[bid] = wsum[0] + wsum[1] + wsum[2] + wsum[3];

    if (m) {
        int k = sh_base + klocal;
        g_valid[0][b][k] = make_float4(c0 + c1, c0 - c1, c2, 0.f);
        g_valid[1][b][k] = make_float4(q0 + q1, q0 - q1, q2, 0.f);
    }
}

// ---------------------------------------------------------------------------
// Kernel 2: dual-direction chamfer from one D. grid (16,32,8), 64 thr.
// Rotating ref ownership: lane processes tile[lane+k]; colmin accumulator
// travels with the ref via shfl(lane+1); after 32 steps it's home at lane.
// |dx|+|dy|+|dz| == max(|du|,|dv|) + |dz| with (u,v) = (x+y, x-y).
// ---------------------------------------------------------------------------
__global__ void __launch_bounds__(TBC)
chamfer_kernel(float* __restrict__ out) {
    int tid = threadIdx.x, lane = tid & 31;
    int b   = blockIdx.z;
    int cnt = g_cnt[b];

    int qn   = (cnt + QCH - 1) / QCH;          // <= 128
    int q_lo = blockIdx.x * qn;
    int q_hi = min(q_lo + qn, cnt);
    int rn   = (cnt + RSP - 1) / RSP;          // <= 64
    int r_lo = blockIdx.y * rn;
    int r_hi = min(r_lo + rn, cnt);

    __shared__ float4 tile[64];                // doubled 32-ref group

    if (q_lo < cnt && r_lo < r_hi) {
        const float4* __restrict__ Q = g_valid[0][b];   // clean (rows)
        const float4* __restrict__ R = g_valid[1][b];   // pred  (cols)
        unsigned int* __restrict__ Mx = g_minbits[0][b];
        unsigned int* __restrict__ My = g_minbits[1][b];
        int src = (lane + 1) & 31;

        for (int g0 = r_lo; g0 < r_hi; g0 += 32) {      // 1-2 groups typ.
            __syncthreads();
            {   // stage doubled tile: slot t holds ref g0+(t&31), pad = FAR
                int jj = tid & 31;
                int ridx = g0 + jj;
                float4 rv = R[ridx < r_hi ? ridx : 0];
                if (ridx >= r_hi) rv = make_float4(FARF, FARF, FARF, 0.f);
                tile[tid] = rv;
            }
            __syncthreads();

            for (int q0 = q_lo; q0 < q_hi; q0 += TBC) { // 1-2 passes typ.
                int q = q0 + tid;                       // < NPAD always
                bool qa = q < q_hi;
                float4 vq = Q[q];
                float qu = qa ? vq.x : FARF;
                float qv = qa ? vq.y : FARF;
                float qz = qa ? vq.z : FARF;
                float rowmin = BIGF, cmv = BIGF;

#pragma unroll
                for (int k = 0; k < 32; ++k) {
                    float4 y = tile[lane + k];          // imm-offset LDS.128
                    float d = fmaxf(fabsf(qu - y.x), fabsf(qv - y.y))
                            + fabsf(qz - y.z);
                    rowmin = fminf(rowmin, d);
                    cmv    = fminf(cmv, d);
                    cmv    = __shfl_sync(0xffffffffu, cmv, src);
                }
                // cmv home: min over this warp's 32 q of d(q, ref g0+lane)
                int ridx = g0 + lane;
                if (ridx < r_hi) atomicMin(&My[ridx], __float_as_uint(cmv));
                if (qa)          atomicMin(&Mx[q],    __float_as_uint(rowmin));
            }
        }
    }

    // -------- hierarchical arrive (8 batch-tasks) --------
    __threadfence();
    __syncthreads();
    __shared__ int task_last;
    if (tid == 0)
        task_last = (atomicAdd(&g_done_task[b], 1u) == ARR - 1);
    __syncthreads();
    if (!task_last) return;

    // -------- per-batch tail: sum both min arrays, store cham_b ----------
    __threadfence();
    {
        const uint4* __restrict__ p0 = (const uint4*)g_minbits[0][b];
        const uint4* __restrict__ p1 = (const uint4*)g_minbits[1][b];
        int nv = cnt >> 2;
        float s = 0.f;
        for (int k = tid; k < nv; k += TBC) {
            uint4 u = p0[k], v = p1[k];
            s += (__uint_as_float(u.x) + __uint_as_float(u.y))
               + (__uint_as_float(u.z) + __uint_as_float(u.w));
            s += (__uint_as_float(v.x) + __uint_as_float(v.y))
               + (__uint_as_float(v.z) + __uint_as_float(v.w));
        }
        if (tid < (cnt & 3)) {
            int k = (cnt & ~3) + tid;
            s += __uint_as_float(g_minbits[0][b][k])
               + __uint_as_float(g_minbits[1][b][k]);
        }
        __shared__ float wsum[2];
#pragma unroll
        for (int o = 16; o > 0; o >>= 1) s += __shfl_down_sync(0xffffffffu, s, o);
        if (lane == 0) wsum[tid >> 5] = s;
        __syncthreads();
        if (tid == 0)
            g_tasksum[b] = (wsum[0] + wsum[1]) / (float)cnt;
    }

    // -------- global arrive; last batch-block combines --------
    __threadfence();
    __syncthreads();
    __shared__ int is_last;
    if (tid == 0)
        is_last = (atomicAdd(&g_done, 1u) == BB - 1);
    __syncthreads();
    if (!is_last) return;

    __threadfence();
    float l1p = g_l1part[tid] + g_l1part[tid + 64];   // 128 partials, 64 thr
    __shared__ float wl[2];
#pragma unroll
    for (int o = 16; o > 0; o >>= 1) l1p += __shfl_down_sync(0xffffffffu, l1p, o);
    if (lane == 0) wl[tid >> 5] = l1p;
    __syncthreads();
    if (tid == 0) {
        float cdsum = 0.f;
#pragma unroll
        for (int t = 0; t < BB; ++t) cdsum += g_tasksum[t];
        float l1num = wl[0] + wl[1];
        int msum = 0;
#pragma unroll
        for (int bb = 0; bb < BB; ++bb) msum += g_cnt[bb];
        float l1 = l1num / 3.0f / (float)msum;
        float cd = cdsum / (float)BB;
        out[0] = l1 + expf(-l1) * cd;
        g_done = 0;                        // reset for next graph replay
    }
    __syncthreads();
    if (tid < BB) { g_cnt[tid] = 0; g_done_task[tid] = 0; }
}

// ---------------------------------------------------------------------------
extern "C" void kernel_launch(void* const* d_in, const int* in_sizes, int n_in,
                              void* d_out, int out_size) {
    const float* pred   = (const float*)d_in[0];
    const float* target = (const float*)d_in[1];
    const int*   mask   = (const int*)  d_in[2];
    const float* points = (const float*)d_in[3];
    float* out = (float*)d_out;

    prep_kernel<<<128, 128>>>(pred, target, mask, points);

    dim3 grid(QCH, RSP, BB);   // (16, 32, 8) = 4096 blocks
    chamfer_kernel<<<grid, TBC>>>(out);
}